// round 1
// baseline (speedup 1.0000x reference)
#include <cuda_runtime.h>
#include <cuda_bf16.h>

#define NN 50000
#define EE 800000
#define HH 4

// Layer 1: IN=128 -> H*64=256 ; Layer 2: 64 -> H*32=128
// Edge MLP: 68 -> 64 -> 2

// ---------------- scratch (device globals; no allocs allowed) ----------------
__device__ __align__(16) float g_xl1[NN * 256];
__device__ __align__(16) float g_a1s[NN * 4];
__device__ __align__(16) float g_a1d[NN * 4];
__device__ __align__(16) float g_ex1[EE * 4];
__device__ __align__(16) float g_den1[NN * 4];
__device__ __align__(16) float g_acc1[NN * 256];
__device__ __align__(16) float g_x2[NN * 64];
__device__ __align__(16) float g_xl2[NN * 128];
__device__ __align__(16) float g_a2s[NN * 4];
__device__ __align__(16) float g_a2d[NN * 4];
__device__ __align__(16) float g_ex2[EE * 4];
__device__ __align__(16) float g_den2[NN * 4];
__device__ __align__(16) float g_acc2[NN * 128];

__device__ __forceinline__ void red_add_v4(float* addr, float4 v) {
    asm volatile("red.global.add.v4.f32 [%0], {%1, %2, %3, %4};"
                 :: "l"(addr), "f"(v.x), "f"(v.y), "f"(v.z), "f"(v.w)
                 : "memory");
}

// ---------------- GEMM: Y[N,M] = X[N,K] @ W[K,M], whole W in smem ----------------
template <int K, int M, int TN, int NPART>
__launch_bounds__(256)
__global__ void gemm_xw(const float* __restrict__ X, const float* __restrict__ W,
                        float* __restrict__ Y, int nN) {
    extern __shared__ float sm[];
    float* Ws = sm;           // K*M
    float* Xs = sm + K * M;   // TN*K
    const int tid = threadIdx.x;
    for (int i = tid; i < K * M; i += 256) Ws[i] = W[i];
    const int n0 = blockIdx.x * TN;
    const int nn = min(TN, nN - n0);
    for (int i = tid; i < nn * K; i += 256) Xs[i] = X[n0 * K + i];
    __syncthreads();

    const int c = tid % M;
    const int part = tid / M;                 // 0..NPART-1
    const int nodes_per_part = TN / NPART;
    const int nbase = part * nodes_per_part;

    for (int nb = 0; nb < nodes_per_part; nb += 8) {
        float acc[8];
#pragma unroll
        for (int j = 0; j < 8; j++) acc[j] = 0.f;
#pragma unroll 4
        for (int k = 0; k < K; k++) {
            float w = Ws[k * M + c];
#pragma unroll
            for (int j = 0; j < 8; j++)
                acc[j] = fmaf(Xs[(nbase + nb + j) * K + k], w, acc[j]);
        }
#pragma unroll
        for (int j = 0; j < 8; j++) {
            int n = nbase + nb + j;
            if (n < nn) Y[(n0 + n) * M + c] = acc[j];
        }
    }
}

// ---------------- attention scores: a[n][h] = dot(xl[n][h*C..], att[h]) ----------------
template <int C>
__global__ void scores_kernel(const float* __restrict__ XL,
                              const float* __restrict__ att_s,
                              const float* __restrict__ att_d,
                              float* __restrict__ as_, float* __restrict__ ad_, int nN) {
    int n = blockIdx.x * 8 + (threadIdx.x >> 5);
    if (n >= nN) return;
    int lane = threadIdx.x & 31;
#pragma unroll
    for (int h = 0; h < HH; h++) {
        float ss = 0.f, sd = 0.f;
#pragma unroll
        for (int c = lane; c < C; c += 32) {
            float v = XL[n * (HH * C) + h * C + c];
            ss += v * att_s[h * C + c];
            sd += v * att_d[h * C + c];
        }
#pragma unroll
        for (int o = 16; o > 0; o >>= 1) {
            ss += __shfl_xor_sync(0xffffffffu, ss, o);
            sd += __shfl_xor_sync(0xffffffffu, sd, o);
        }
        if (lane == 0) { as_[n * 4 + h] = ss; ad_[n * 4 + h] = sd; }
    }
}

// ---------------- per-edge: ex = exp(leaky(a_src+a_dst)); den[dst] += ex ----------------
__global__ void edge_exp_kernel(const int* __restrict__ src, const int* __restrict__ dst,
                                const float* __restrict__ as_, const float* __restrict__ ad_,
                                float* __restrict__ ex, float* __restrict__ den) {
    int e = blockIdx.x * blockDim.x + threadIdx.x;
    if (e >= EE) return;
    int s = src[e], d = dst[e];
    const float4 a = *(const float4*)(as_ + s * 4);
    const float4 b = *(const float4*)(ad_ + d * 4);
    float4 r;
    float t;
    t = a.x + b.x; t = fmaxf(t, 0.f) + 0.2f * fminf(t, 0.f); r.x = expf(t);
    t = a.y + b.y; t = fmaxf(t, 0.f) + 0.2f * fminf(t, 0.f); r.y = expf(t);
    t = a.z + b.z; t = fmaxf(t, 0.f) + 0.2f * fminf(t, 0.f); r.z = expf(t);
    t = a.w + b.w; t = fmaxf(t, 0.f) + 0.2f * fminf(t, 0.f); r.w = expf(t);
    *(float4*)(ex + e * 4) = r;
    red_add_v4(den + d * 4, r);
}

// ---------------- aggregation: acc[dst] += xl[src] * ex[e][h] (warp per edge) ----------------
template <int C>   // floats per row = 4*C; float4s per row = C
__global__ void aggregate_kernel(const int* __restrict__ src, const int* __restrict__ dst,
                                 const float* __restrict__ xl, const float* __restrict__ ex,
                                 float* __restrict__ acc) {
    int gw = (blockIdx.x * blockDim.x + threadIdx.x) >> 5;
    if (gw >= EE) return;
    int lane = threadIdx.x & 31;
    int s = src[gw], d = dst[gw];
    const float4* xrow = (const float4*)(xl + (size_t)s * (4 * C));
    float* arow = acc + (size_t)d * (4 * C);
#pragma unroll
    for (int i = lane; i < C; i += 32) {
        int h = (i * 4) / C;
        float w = ex[gw * 4 + h];
        float4 v = xrow[i];
        v.x *= w; v.y *= w; v.z *= w; v.w *= w;
        red_add_v4(arow + i * 4, v);
    }
}

// ---------------- finalize: out[n][c] = mean_h(acc[n][h][c]/den[n][h]) + bias[c] ----------------
template <int C>
__global__ void finalize_kernel(const float* __restrict__ acc, const float* __restrict__ den,
                                const float* __restrict__ bias, float* __restrict__ out, int nN) {
    int idx = blockIdx.x * blockDim.x + threadIdx.x;
    if (idx >= nN * C) return;
    int n = idx / C, c = idx % C;
    float s = 0.f;
#pragma unroll
    for (int h = 0; h < HH; h++)
        s += acc[n * (HH * C) + h * C + c] / (den[n * 4 + h] + 1e-16f);
    out[idx] = 0.25f * s + bias[c];
}

// ---------------- edge MLP: [out_src(32), alpha(4), out_dst(32)] -> 64 relu -> 2 ----------------
__launch_bounds__(256)
__global__ void edge_mlp_kernel(const int* __restrict__ src, const int* __restrict__ dst,
                                const float* __restrict__ outn, const float* __restrict__ ex2,
                                const float* __restrict__ den2,
                                const float* __restrict__ mW1, const float* __restrict__ mb1,
                                const float* __restrict__ mW2, const float* __restrict__ mb2,
                                float* __restrict__ eo) {
    __shared__ float4 W1s4[68 * 16];   // 68 x 64
    __shared__ float b1s[64];
    __shared__ float W2s[64 * 2];
    __shared__ float b2s[2];
    int tid = threadIdx.x;
    for (int i = tid; i < 68 * 64; i += 256) ((float*)W1s4)[i] = mW1[i];
    for (int i = tid; i < 64; i += 256) b1s[i] = mb1[i];
    for (int i = tid; i < 128; i += 256) W2s[i] = mW2[i];
    if (tid < 2) b2s[tid] = mb2[tid];
    __syncthreads();

    int e = blockIdx.x * blockDim.x + tid;
    if (e >= EE) return;
    int s = src[e], d = dst[e];

    float feat[68];   // dynamic-indexed -> local memory (1 LDL per 80 insts, fine)
    const float4* po = (const float4*)outn;
#pragma unroll
    for (int i = 0; i < 8; i++) {
        float4 t = po[s * 8 + i];
        feat[4 * i + 0] = t.x; feat[4 * i + 1] = t.y;
        feat[4 * i + 2] = t.z; feat[4 * i + 3] = t.w;
    }
#pragma unroll
    for (int h = 0; h < 4; h++)
        feat[32 + h] = ex2[e * 4 + h] / (den2[d * 4 + h] + 1e-16f);
#pragma unroll
    for (int i = 0; i < 8; i++) {
        float4 t = po[d * 8 + i];
        feat[36 + 4 * i + 0] = t.x; feat[36 + 4 * i + 1] = t.y;
        feat[36 + 4 * i + 2] = t.z; feat[36 + 4 * i + 3] = t.w;
    }

    float acc[64];
#pragma unroll
    for (int j = 0; j < 64; j++) acc[j] = b1s[j];
#pragma unroll 1
    for (int k = 0; k < 68; k++) {
        float f = feat[k];
#pragma unroll
        for (int j4 = 0; j4 < 16; j4++) {
            float4 w = W1s4[k * 16 + j4];
            acc[4 * j4 + 0] = fmaf(f, w.x, acc[4 * j4 + 0]);
            acc[4 * j4 + 1] = fmaf(f, w.y, acc[4 * j4 + 1]);
            acc[4 * j4 + 2] = fmaf(f, w.z, acc[4 * j4 + 2]);
            acc[4 * j4 + 3] = fmaf(f, w.w, acc[4 * j4 + 3]);
        }
    }
    float o0 = b2s[0], o1 = b2s[1];
#pragma unroll
    for (int j = 0; j < 64; j++) {
        float h = fmaxf(acc[j], 0.f);
        o0 = fmaf(h, W2s[j * 2 + 0], o0);
        o1 = fmaf(h, W2s[j * 2 + 1], o1);
    }
    ((float2*)eo)[e] = make_float2(o0, o1);
}

// ---------------- launch ----------------
extern "C" void kernel_launch(void* const* d_in, const int* in_sizes, int n_in,
                              void* d_out, int out_size) {
    const float* x    = (const float*)d_in[0];
    const int*   ei   = (const int*)d_in[1];
    const float* W1   = (const float*)d_in[4];
    const float* a1s  = (const float*)d_in[5];
    const float* a1d  = (const float*)d_in[6];
    const float* b1   = (const float*)d_in[7];
    const float* W3   = (const float*)d_in[8];
    const float* a3s  = (const float*)d_in[9];
    const float* a3d  = (const float*)d_in[10];
    const float* b3   = (const float*)d_in[11];
    const float* mW1  = (const float*)d_in[12];
    const float* mb1  = (const float*)d_in[13];
    const float* mW2  = (const float*)d_in[14];
    const float* mb2  = (const float*)d_in[15];

    const int* src = ei;
    const int* dst = ei + EE;

    float* out_nodes = (float*)d_out;             // N*32
    float* out_edges = (float*)d_out + NN * 32;   // E*2

    float *p_acc1, *p_acc2, *p_den1, *p_den2;
    cudaGetSymbolAddress((void**)&p_acc1, g_acc1);
    cudaGetSymbolAddress((void**)&p_acc2, g_acc2);
    cudaGetSymbolAddress((void**)&p_den1, g_den1);
    cudaGetSymbolAddress((void**)&p_den2, g_den2);
    float *p_xl1, *p_xl2, *p_x2, *p_a1s, *p_a1d, *p_a2s, *p_a2d, *p_ex1, *p_ex2;
    cudaGetSymbolAddress((void**)&p_xl1, g_xl1);
    cudaGetSymbolAddress((void**)&p_xl2, g_xl2);
    cudaGetSymbolAddress((void**)&p_x2,  g_x2);
    cudaGetSymbolAddress((void**)&p_a1s, g_a1s);
    cudaGetSymbolAddress((void**)&p_a1d, g_a1d);
    cudaGetSymbolAddress((void**)&p_a2s, g_a2s);
    cudaGetSymbolAddress((void**)&p_a2d, g_a2d);
    cudaGetSymbolAddress((void**)&p_ex1, g_ex1);
    cudaGetSymbolAddress((void**)&p_ex2, g_ex2);

    cudaMemsetAsync(p_acc1, 0, (size_t)NN * 256 * 4);
    cudaMemsetAsync(p_acc2, 0, (size_t)NN * 128 * 4);
    cudaMemsetAsync(p_den1, 0, (size_t)NN * 4 * 4);
    cudaMemsetAsync(p_den2, 0, (size_t)NN * 4 * 4);

    // Layer 1
    cudaFuncSetAttribute(gemm_xw<128, 256, 32, 1>,
                         cudaFuncAttributeMaxDynamicSharedMemorySize, 147456);
    gemm_xw<128, 256, 32, 1><<<(NN + 31) / 32, 256, 147456>>>(x, W1, p_xl1, NN);
    scores_kernel<64><<<(NN + 7) / 8, 256>>>(p_xl1, a1s, a1d, p_a1s, p_a1d, NN);
    edge_exp_kernel<<<(EE + 255) / 256, 256>>>(src, dst, p_a1s, p_a1d, p_ex1, p_den1);
    aggregate_kernel<64><<<EE / 8, 256>>>(src, dst, p_xl1, p_ex1, p_acc1);
    finalize_kernel<64><<<(NN * 64 + 255) / 256, 256>>>(p_acc1, p_den1, b1, p_x2, NN);

    // Layer 2
    gemm_xw<64, 128, 32, 2><<<(NN + 31) / 32, 256, 40960>>>(p_x2, W3, p_xl2, NN);
    scores_kernel<32><<<(NN + 7) / 8, 256>>>(p_xl2, a3s, a3d, p_a2s, p_a2d, NN);
    edge_exp_kernel<<<(EE + 255) / 256, 256>>>(src, dst, p_a2s, p_a2d, p_ex2, p_den2);
    aggregate_kernel<32><<<EE / 8, 256>>>(src, dst, p_xl2, p_ex2, p_acc2);
    finalize_kernel<32><<<(NN * 32 + 255) / 256, 256>>>(p_acc2, p_den2, b3, out_nodes, NN);

    // Edge MLP
    edge_mlp_kernel<<<(EE + 255) / 256, 256>>>(src, dst, out_nodes, p_ex2, p_den2,
                                               mW1, mb1, mW2, mb2, out_edges);
}

// round 2
// speedup vs baseline: 1.5964x; 1.5964x over previous
#include <cuda_runtime.h>
#include <cuda_bf16.h>

#define NN 50000
#define EE 800000
#define HH 4

typedef unsigned long long ull;

// ---------------- scratch ----------------
__device__ __align__(16) float g_xl1[NN * 256];
__device__ __align__(16) float g_a1s[NN * 4];
__device__ __align__(16) float g_a1d[NN * 4];
__device__ __align__(16) float g_ex1[EE * 4];
__device__ __align__(16) float g_den1[NN * 4];
__device__ __align__(16) float g_x2[NN * 64];
__device__ __align__(16) float g_xl2[NN * 128];
__device__ __align__(16) float g_a2s[NN * 4];
__device__ __align__(16) float g_a2d[NN * 4];
__device__ __align__(16) float g_ex2[EE * 4];
__device__ __align__(16) float g_den2[NN * 4];
__device__ int  g_deg[NN];
__device__ int  g_ptr[NN];
__device__ int  g_pos[NN];
__device__ int  g_bsum[128];
__device__ __align__(8) int2 g_eid[EE];

__device__ __forceinline__ void red_add_v4(float* addr, float4 v) {
    asm volatile("red.global.add.v4.f32 [%0], {%1, %2, %3, %4};"
                 :: "l"(addr), "f"(v.x), "f"(v.y), "f"(v.z), "f"(v.w)
                 : "memory");
}
__device__ __forceinline__ ull ffma2(ull a, ull b, ull c) {
    ull d;
    asm("fma.rn.f32x2 %0, %1, %2, %3;" : "=l"(d) : "l"(a), "l"(b), "l"(c));
    return d;
}
__device__ __forceinline__ ull pack2(float x, float y) {
    ull d; asm("mov.b64 %0, {%1, %2};" : "=l"(d) : "f"(x), "f"(y)); return d;
}
__device__ __forceinline__ void unpack2(ull v, float& x, float& y) {
    asm("mov.b64 {%0, %1}, %2;" : "=f"(x), "=f"(y) : "l"(v));
}

// ---------------- CSR build ----------------
__global__ void hist_kernel(const int* __restrict__ dst, int* __restrict__ deg) {
    int e = blockIdx.x * blockDim.x + threadIdx.x;
    if (e < EE) atomicAdd(&deg[dst[e]], 1);
}
__global__ void scanA_kernel(const int* __restrict__ deg, int* __restrict__ out,
                             int* __restrict__ bsum) {
    __shared__ int sm[512];
    int t = threadIdx.x;
    int g = blockIdx.x * 512 + t;
    int v = (g < NN) ? deg[g] : 0;
    sm[t] = v; __syncthreads();
    for (int o = 1; o < 512; o <<= 1) {
        int tt = (t >= o) ? sm[t - o] : 0;
        __syncthreads();
        sm[t] += tt;
        __syncthreads();
    }
    if (g < NN) out[g] = sm[t] - v;            // exclusive
    if (t == 511) bsum[blockIdx.x] = sm[511];
}
__global__ void scanB_kernel(int* __restrict__ bsum, int nb) {
    __shared__ int sm[128];
    int t = threadIdx.x;
    int v = (t < nb) ? bsum[t] : 0;
    sm[t] = v; __syncthreads();
    for (int o = 1; o < 128; o <<= 1) {
        int tt = (t >= o) ? sm[t - o] : 0;
        __syncthreads();
        sm[t] += tt;
        __syncthreads();
    }
    if (t < nb) bsum[t] = sm[t] - v;           // exclusive
}
__global__ void scanC_kernel(int* __restrict__ ptr, const int* __restrict__ bsum,
                             int* __restrict__ pos) {
    int g = blockIdx.x * 512 + threadIdx.x;
    if (g < NN) {
        int v = ptr[g] + bsum[blockIdx.x];
        ptr[g] = v;
        pos[g] = v;
    }
}
__global__ void scatter_kernel(const int* __restrict__ src, const int* __restrict__ dst,
                               int* __restrict__ pos, int2* __restrict__ eid) {
    int e = blockIdx.x * blockDim.x + threadIdx.x;
    if (e < EE) {
        int p = atomicAdd(&pos[dst[e]], 1);
        eid[p] = make_int2(e, src[e]);
    }
}

// ---------------- GEMM: Y[N,M] = X[N,K] @ W[K,M], f32x2 packed ----------------
template <int K, int M, int TN>
__launch_bounds__(256)
__global__ void gemm_xw(const float* __restrict__ X, const float* __restrict__ W,
                        float* __restrict__ Y, int nN) {
    extern __shared__ float sm[];
    float* Ws = sm;           // K*M
    float* Xs = sm + K * M;   // TN*K
    constexpr int CG = M / 4;
    constexpr int PARTS = 256 / CG;
    constexpr int NP = TN / PARTS;
    const int tid = threadIdx.x;
    for (int i = tid; i < K * M; i += 256) Ws[i] = W[i];
    const int n0 = blockIdx.x * TN;
    const int nn = min(TN, nN - n0);
    for (int i = tid; i < nn * K; i += 256) Xs[i] = X[(size_t)n0 * K + i];
    __syncthreads();

    const int cg = tid % CG;
    const int part = tid / CG;
    const int nbase = part * NP;

    for (int nb = 0; nb < NP; nb += 8) {
        ull a2[8][2];
#pragma unroll
        for (int j = 0; j < 8; j++) { a2[j][0] = 0ull; a2[j][1] = 0ull; }
#pragma unroll 2
        for (int k0 = 0; k0 < K; k0 += 4) {
            float4 xv[8];
#pragma unroll
            for (int j = 0; j < 8; j++)
                xv[j] = *(const float4*)&Xs[(nbase + nb + j) * K + k0];
#pragma unroll
            for (int kk = 0; kk < 4; kk++) {
                ulonglong2 wp = *(const ulonglong2*)&Ws[(k0 + kk) * M + cg * 4];
#pragma unroll
                for (int j = 0; j < 8; j++) {
                    float xk = (kk == 0) ? xv[j].x : (kk == 1) ? xv[j].y
                             : (kk == 2) ? xv[j].z : xv[j].w;
                    ull xx = pack2(xk, xk);
                    a2[j][0] = ffma2(xx, wp.x, a2[j][0]);
                    a2[j][1] = ffma2(xx, wp.y, a2[j][1]);
                }
            }
        }
#pragma unroll
        for (int j = 0; j < 8; j++) {
            int n = nbase + nb + j;
            if (n < nn) {
                ulonglong2 o; o.x = a2[j][0]; o.y = a2[j][1];
                *(ulonglong2*)&Y[(size_t)(n0 + n) * M + cg * 4] = o;
            }
        }
    }
}

// ---------------- attention scores ----------------
template <int C>
__global__ void scores_kernel(const float* __restrict__ XL,
                              const float* __restrict__ att_s,
                              const float* __restrict__ att_d,
                              float* __restrict__ as_, float* __restrict__ ad_, int nN) {
    int n = blockIdx.x * 8 + (threadIdx.x >> 5);
    if (n >= nN) return;
    int lane = threadIdx.x & 31;
#pragma unroll
    for (int h = 0; h < HH; h++) {
        float ss = 0.f, sd = 0.f;
#pragma unroll
        for (int c = lane; c < C; c += 32) {
            float v = XL[(size_t)n * (HH * C) + h * C + c];
            ss += v * att_s[h * C + c];
            sd += v * att_d[h * C + c];
        }
#pragma unroll
        for (int o = 16; o > 0; o >>= 1) {
            ss += __shfl_xor_sync(0xffffffffu, ss, o);
            sd += __shfl_xor_sync(0xffffffffu, sd, o);
        }
        if (lane == 0) { as_[n * 4 + h] = ss; ad_[n * 4 + h] = sd; }
    }
}

// ---------------- per-edge exp + denominator ----------------
__global__ void edge_exp_kernel(const int* __restrict__ src, const int* __restrict__ dst,
                                const float* __restrict__ as_, const float* __restrict__ ad_,
                                float* __restrict__ ex, float* __restrict__ den) {
    int e = blockIdx.x * blockDim.x + threadIdx.x;
    if (e >= EE) return;
    int s = src[e], d = dst[e];
    const float4 a = *(const float4*)(as_ + (size_t)s * 4);
    const float4 b = *(const float4*)(ad_ + (size_t)d * 4);
    float4 r; float t;
    t = a.x + b.x; t = fmaxf(t, 0.f) + 0.2f * fminf(t, 0.f); r.x = expf(t);
    t = a.y + b.y; t = fmaxf(t, 0.f) + 0.2f * fminf(t, 0.f); r.y = expf(t);
    t = a.z + b.z; t = fmaxf(t, 0.f) + 0.2f * fminf(t, 0.f); r.z = expf(t);
    t = a.w + b.w; t = fmaxf(t, 0.f) + 0.2f * fminf(t, 0.f); r.w = expf(t);
    *(float4*)(ex + (size_t)e * 4) = r;
    red_add_v4(den + (size_t)d * 4, r);
}

// ---------------- CSR aggregation, C=64 (layer 1), fused finalize ----------------
__launch_bounds__(256)
__global__ void agg_csr64(const int2* __restrict__ eid, const int* __restrict__ ptr,
                          const int* __restrict__ deg, const float* __restrict__ xl,
                          const float* __restrict__ ex, const float* __restrict__ den,
                          const float* __restrict__ bias, float* __restrict__ out) {
    int n = blockIdx.x * 8 + (threadIdx.x >> 5);
    if (n >= NN) return;
    int lane = threadIdx.x & 31;
    int p0 = ptr[n], dg = deg[n];
    float4 a0 = make_float4(0.f, 0.f, 0.f, 0.f), a1 = a0;
    int2 nx = (dg > 0) ? eid[p0] : make_int2(0, 0);
    for (int j = 0; j < dg; j++) {
        int2 cur = nx;
        if (j + 1 < dg) nx = eid[p0 + j + 1];
        float4 w4 = *(const float4*)(ex + (size_t)cur.x * 4);
        const float4* xr = (const float4*)(xl + (size_t)cur.y * 256);
        float w0 = (lane < 16) ? w4.x : w4.y;
        float w1 = (lane < 16) ? w4.z : w4.w;
        float4 v0 = xr[lane];
        float4 v1 = xr[lane + 32];
        a0.x = fmaf(v0.x, w0, a0.x); a0.y = fmaf(v0.y, w0, a0.y);
        a0.z = fmaf(v0.z, w0, a0.z); a0.w = fmaf(v0.w, w0, a0.w);
        a1.x = fmaf(v1.x, w1, a1.x); a1.y = fmaf(v1.y, w1, a1.y);
        a1.z = fmaf(v1.z, w1, a1.z); a1.w = fmaf(v1.w, w1, a1.w);
    }
    float4 dn = *(const float4*)(den + (size_t)n * 4);
    float d0 = 1.f / (((lane < 16) ? dn.x : dn.y) + 1e-16f);
    float d1 = 1.f / (((lane < 16) ? dn.z : dn.w) + 1e-16f);
    float4 t;
    t.x = a0.x * d0 + a1.x * d1; t.y = a0.y * d0 + a1.y * d1;
    t.z = a0.z * d0 + a1.z * d1; t.w = a0.w * d0 + a1.w * d1;
    t.x += __shfl_xor_sync(0xffffffffu, t.x, 16);
    t.y += __shfl_xor_sync(0xffffffffu, t.y, 16);
    t.z += __shfl_xor_sync(0xffffffffu, t.z, 16);
    t.w += __shfl_xor_sync(0xffffffffu, t.w, 16);
    if (lane < 16) {
        float4 b4 = *(const float4*)(bias + 4 * lane);
        float4 o;
        o.x = 0.25f * t.x + b4.x; o.y = 0.25f * t.y + b4.y;
        o.z = 0.25f * t.z + b4.z; o.w = 0.25f * t.w + b4.w;
        *(float4*)(out + (size_t)n * 64 + 4 * lane) = o;
    }
}

// ---------------- CSR aggregation, C=32 (layer 2), fused finalize ----------------
__launch_bounds__(256)
__global__ void agg_csr32(const int2* __restrict__ eid, const int* __restrict__ ptr,
                          const int* __restrict__ deg, const float* __restrict__ xl,
                          const float* __restrict__ ex, const float* __restrict__ den,
                          const float* __restrict__ bias, float* __restrict__ out) {
    int n = blockIdx.x * 8 + (threadIdx.x >> 5);
    if (n >= NN) return;
    int lane = threadIdx.x & 31;
    int p0 = ptr[n], dg = deg[n];
    int h = lane >> 3;   // lane/8: head index for this lane's float4
    float4 a0 = make_float4(0.f, 0.f, 0.f, 0.f);
    int2 nx = (dg > 0) ? eid[p0] : make_int2(0, 0);
    for (int j = 0; j < dg; j++) {
        int2 cur = nx;
        if (j + 1 < dg) nx = eid[p0 + j + 1];
        float w = ex[(size_t)cur.x * 4 + h];
        const float4* xr = (const float4*)(xl + (size_t)cur.y * 128);
        float4 v0 = xr[lane];
        a0.x = fmaf(v0.x, w, a0.x); a0.y = fmaf(v0.y, w, a0.y);
        a0.z = fmaf(v0.z, w, a0.z); a0.w = fmaf(v0.w, w, a0.w);
    }
    float dh = 1.f / (den[(size_t)n * 4 + h] + 1e-16f);
    float4 t;
    t.x = a0.x * dh; t.y = a0.y * dh; t.z = a0.z * dh; t.w = a0.w * dh;
    t.x += __shfl_xor_sync(0xffffffffu, t.x, 8);
    t.y += __shfl_xor_sync(0xffffffffu, t.y, 8);
    t.z += __shfl_xor_sync(0xffffffffu, t.z, 8);
    t.w += __shfl_xor_sync(0xffffffffu, t.w, 8);
    t.x += __shfl_xor_sync(0xffffffffu, t.x, 16);
    t.y += __shfl_xor_sync(0xffffffffu, t.y, 16);
    t.z += __shfl_xor_sync(0xffffffffu, t.z, 16);
    t.w += __shfl_xor_sync(0xffffffffu, t.w, 16);
    if (lane < 8) {
        float4 b4 = *(const float4*)(bias + 4 * lane);
        float4 o;
        o.x = 0.25f * t.x + b4.x; o.y = 0.25f * t.y + b4.y;
        o.z = 0.25f * t.z + b4.z; o.w = 0.25f * t.w + b4.w;
        *(float4*)(out + (size_t)n * 32 + 4 * lane) = o;
    }
}

// ---------------- edge MLP (f32x2 packed) ----------------
__device__ __forceinline__ void mlp_k(ull* acc, const ulonglong2* W1s, int k, float f) {
    ull ff = pack2(f, f);
#pragma unroll
    for (int q = 0; q < 16; q++) {
        ulonglong2 wp = W1s[k * 16 + q];
        acc[2 * q]     = ffma2(ff, wp.x, acc[2 * q]);
        acc[2 * q + 1] = ffma2(ff, wp.y, acc[2 * q + 1]);
    }
}

__launch_bounds__(256)
__global__ void edge_mlp_kernel(const int* __restrict__ src, const int* __restrict__ dst,
                                const float* __restrict__ outn, const float* __restrict__ ex2,
                                const float* __restrict__ den2,
                                const float* __restrict__ mW1, const float* __restrict__ mb1,
                                const float* __restrict__ mW2, const float* __restrict__ mb2,
                                float* __restrict__ eo) {
    __shared__ ulonglong2 W1s[68 * 16];  // [k][q]: cols 4q..4q+3 as two f32x2 pairs
    __shared__ ull B1s[32];
    __shared__ ull W2s[64];              // (W2[j][0], W2[j][1])
    __shared__ float B2s[2];
    int tid = threadIdx.x;
    for (int i = tid; i < 68 * 64; i += 256) ((float*)W1s)[i] = mW1[i];
    for (int i = tid; i < 64; i += 256) ((float*)B1s)[i] = mb1[i];
    for (int i = tid; i < 128; i += 256) ((float*)W2s)[i] = mW2[i];
    if (tid < 2) B2s[tid] = mb2[tid];
    __syncthreads();

    int e = blockIdx.x * 256 + tid;
    if (e >= EE) return;
    int s = src[e], d = dst[e];

    ull acc[32];
#pragma unroll
    for (int q = 0; q < 32; q++) acc[q] = B1s[q];

    const float4* po = (const float4*)outn;
#pragma unroll
    for (int i = 0; i < 8; i++) {
        float4 t = po[(size_t)s * 8 + i];
        mlp_k(acc, W1s, 4 * i + 0, t.x);
        mlp_k(acc, W1s, 4 * i + 1, t.y);
        mlp_k(acc, W1s, 4 * i + 2, t.z);
        mlp_k(acc, W1s, 4 * i + 3, t.w);
    }
    {
        float4 a4 = *(const float4*)(ex2 + (size_t)e * 4);
        float4 dn = *(const float4*)(den2 + (size_t)d * 4);
        mlp_k(acc, W1s, 32, a4.x / (dn.x + 1e-16f));
        mlp_k(acc, W1s, 33, a4.y / (dn.y + 1e-16f));
        mlp_k(acc, W1s, 34, a4.z / (dn.z + 1e-16f));
        mlp_k(acc, W1s, 35, a4.w / (dn.w + 1e-16f));
    }
#pragma unroll
    for (int i = 0; i < 8; i++) {
        float4 t = po[(size_t)d * 8 + i];
        mlp_k(acc, W1s, 36 + 4 * i + 0, t.x);
        mlp_k(acc, W1s, 36 + 4 * i + 1, t.y);
        mlp_k(acc, W1s, 36 + 4 * i + 2, t.z);
        mlp_k(acc, W1s, 36 + 4 * i + 3, t.w);
    }

    ull o2 = pack2(B2s[0], B2s[1]);
#pragma unroll
    for (int p = 0; p < 32; p++) {
        float lo, hi;
        unpack2(acc[p], lo, hi);
        lo = fmaxf(lo, 0.f); hi = fmaxf(hi, 0.f);
        o2 = ffma2(pack2(lo, lo), W2s[2 * p], o2);
        o2 = ffma2(pack2(hi, hi), W2s[2 * p + 1], o2);
    }
    float o0, o1;
    unpack2(o2, o0, o1);
    ((float2*)eo)[e] = make_float2(o0, o1);
}

// ---------------- launch ----------------
extern "C" void kernel_launch(void* const* d_in, const int* in_sizes, int n_in,
                              void* d_out, int out_size) {
    const float* x    = (const float*)d_in[0];
    const int*   ei   = (const int*)d_in[1];
    const float* W1   = (const float*)d_in[4];
    const float* a1s  = (const float*)d_in[5];
    const float* a1d  = (const float*)d_in[6];
    const float* b1   = (const float*)d_in[7];
    const float* W3   = (const float*)d_in[8];
    const float* a3s  = (const float*)d_in[9];
    const float* a3d  = (const float*)d_in[10];
    const float* b3   = (const float*)d_in[11];
    const float* mW1  = (const float*)d_in[12];
    const float* mb1  = (const float*)d_in[13];
    const float* mW2  = (const float*)d_in[14];
    const float* mb2  = (const float*)d_in[15];

    const int* src = ei;
    const int* dst = ei + EE;

    float* out_nodes = (float*)d_out;             // N*32
    float* out_edges = (float*)d_out + NN * 32;   // E*2

    float *p_xl1, *p_xl2, *p_x2, *p_a1s, *p_a1d, *p_a2s, *p_a2d, *p_ex1, *p_ex2;
    float *p_den1, *p_den2;
    int *p_deg, *p_ptr, *p_pos, *p_bsum;
    int2 *p_eid;
    cudaGetSymbolAddress((void**)&p_xl1, g_xl1);
    cudaGetSymbolAddress((void**)&p_xl2, g_xl2);
    cudaGetSymbolAddress((void**)&p_x2,  g_x2);
    cudaGetSymbolAddress((void**)&p_a1s, g_a1s);
    cudaGetSymbolAddress((void**)&p_a1d, g_a1d);
    cudaGetSymbolAddress((void**)&p_a2s, g_a2s);
    cudaGetSymbolAddress((void**)&p_a2d, g_a2d);
    cudaGetSymbolAddress((void**)&p_ex1, g_ex1);
    cudaGetSymbolAddress((void**)&p_ex2, g_ex2);
    cudaGetSymbolAddress((void**)&p_den1, g_den1);
    cudaGetSymbolAddress((void**)&p_den2, g_den2);
    cudaGetSymbolAddress((void**)&p_deg, g_deg);
    cudaGetSymbolAddress((void**)&p_ptr, g_ptr);
    cudaGetSymbolAddress((void**)&p_pos, g_pos);
    cudaGetSymbolAddress((void**)&p_bsum, g_bsum);
    cudaGetSymbolAddress((void**)&p_eid, g_eid);

    cudaMemsetAsync(p_den1, 0, (size_t)NN * 4 * 4);
    cudaMemsetAsync(p_den2, 0, (size_t)NN * 4 * 4);
    cudaMemsetAsync(p_deg, 0, (size_t)NN * 4);

    const int NB = (NN + 511) / 512;  // 98

    // CSR build (edge list sorted by dst)
    hist_kernel<<<(EE + 255) / 256, 256>>>(dst, p_deg);
    scanA_kernel<<<NB, 512>>>(p_deg, p_ptr, p_bsum);
    scanB_kernel<<<1, 128>>>(p_bsum, NB);
    scanC_kernel<<<NB, 512>>>(p_ptr, p_bsum, p_pos);
    scatter_kernel<<<(EE + 255) / 256, 256>>>(src, dst, p_pos, p_eid);

    // Layer 1
    cudaFuncSetAttribute(gemm_xw<128, 256, 128>,
                         cudaFuncAttributeMaxDynamicSharedMemorySize, 196608);
    gemm_xw<128, 256, 128><<<(NN + 127) / 128, 256, 196608>>>(x, W1, p_xl1, NN);
    scores_kernel<64><<<(NN + 7) / 8, 256>>>(p_xl1, a1s, a1d, p_a1s, p_a1d, NN);
    edge_exp_kernel<<<(EE + 255) / 256, 256>>>(src, dst, p_a1s, p_a1d, p_ex1, p_den1);
    agg_csr64<<<(NN + 7) / 8, 256>>>(p_eid, p_ptr, p_deg, p_xl1, p_ex1, p_den1, b1, p_x2);

    // Layer 2
    cudaFuncSetAttribute(gemm_xw<64, 128, 128>,
                         cudaFuncAttributeMaxDynamicSharedMemorySize, 65536);
    gemm_xw<64, 128, 128><<<(NN + 127) / 128, 256, 65536>>>(p_x2, W3, p_xl2, NN);
    scores_kernel<32><<<(NN + 7) / 8, 256>>>(p_xl2, a3s, a3d, p_a2s, p_a2d, NN);
    edge_exp_kernel<<<(EE + 255) / 256, 256>>>(src, dst, p_a2s, p_a2d, p_ex2, p_den2);
    agg_csr32<<<(NN + 7) / 8, 256>>>(p_eid, p_ptr, p_deg, p_xl2, p_ex2, p_den2, b3, out_nodes);

    // Edge MLP
    edge_mlp_kernel<<<(EE + 255) / 256, 256>>>(src, dst, out_nodes, p_ex2, p_den2,
                                               mW1, mb1, mW2, mb2, out_edges);
}